// round 7
// baseline (speedup 1.0000x reference)
#include <cuda_runtime.h>
#include <math.h>
#include <stdint.h>

#define HDIM 1024
#define MD   2048
#define LMEM 16384
#define NH   8
#define DH   128
#define TPB  256
#define TR   8
#define NT   (LMEM/TR)     // 2048 tiles
#define GB   152           // GB300 has 152 SMs
#define QSCALE 0.08838834764831845f   // 1/sqrt(128)

typedef unsigned long long u64;

// __device__ scratch (no allocations allowed)
__device__ float g_w8[MD*NH];
__device__ float g_pm[GB*NH];
__device__ float g_pz[GB*NH];
__device__ float g_pp[GB*NH*MD];
__device__ float g_pooled[NH*MD];
__device__ float g_feat[HDIM];

__device__ __forceinline__ float warp_sum(float v){
#pragma unroll
    for (int o = 16; o; o >>= 1) v += __shfl_xor_sync(0xffffffffu, v, o);
    return v;
}
__device__ __forceinline__ float warp_max(float v){
#pragma unroll
    for (int o = 16; o; o >>= 1) v = fmaxf(v, __shfl_xor_sync(0xffffffffu, v, o));
    return v;
}

// ---- packed f32x2 helpers (sm_103a) ----
__device__ __forceinline__ u64 pk(float lo, float hi){
    u64 r; asm("mov.b64 %0,{%1,%2};" : "=l"(r) : "f"(lo), "f"(hi)); return r;
}
__device__ __forceinline__ u64 dup2(float v){ return pk(v, v); }
__device__ __forceinline__ u64 fma2(u64 a, u64 b, u64 c){
    u64 d; asm("fma.rn.f32x2 %0,%1,%2,%3;" : "=l"(d) : "l"(a), "l"(b), "l"(c)); return d;
}
__device__ __forceinline__ u64 mul2(u64 a, u64 b){
    u64 d; asm("mul.rn.f32x2 %0,%1,%2;" : "=l"(d) : "l"(a), "l"(b)); return d;
}
__device__ __forceinline__ u64 add2(u64 a, u64 b){
    u64 d; asm("add.rn.f32x2 %0,%1,%2;" : "=l"(d) : "l"(a), "l"(b)); return d;
}
__device__ __forceinline__ void upk(u64 v, float& lo, float& hi){
    asm("mov.b64 {%0,%1},%2;" : "=f"(lo), "=f"(hi) : "l"(v));
}
__device__ __forceinline__ u64 warp_sum2(u64 v){
#pragma unroll
    for (int o = 16; o; o >>= 1) v = add2(v, __shfl_xor_sync(0xffffffffu, v, o));
    return v;
}

__device__ __forceinline__ void cp16(float* dst, const float* src){
    uint32_t s = (uint32_t)__cvta_generic_to_shared(dst);
    asm volatile("cp.async.cg.shared.global [%0], [%1], 16;" :: "r"(s), "l"(src));
}

// -------- k_w8 (q fused in): w8[m][n] = QSCALE * sum_i q[i*8+n] * Wk[i*8+n][m] --------
__global__ __launch_bounds__(TPB) void k_w8(const float* __restrict__ x,
                                            const float* __restrict__ Wq,
                                            const float* __restrict__ bq,
                                            const float* __restrict__ Wk){
    int n  = blockIdx.x & 7;
    int m  = (blockIdx.x >> 3) * TPB + threadIdx.x;
    int lane = threadIdx.x & 31, wid = threadIdx.x >> 5;
    __shared__ float qs[DH];
    const float4* xr = (const float4*)x;
    // each of 8 warps computes 16 q entries for this head
#pragma unroll 4
    for (int j = 0; j < 16; j++){
        int i = wid * 16 + j;
        int h = i * 8 + n;
        const float4* wr = (const float4*)(Wq + (size_t)h * HDIM);
        float acc = 0.f;
#pragma unroll
        for (int u = 0; u < 8; u++){
            float4 a = wr[lane + 32*u];
            float4 b = xr[lane + 32*u];
            acc += a.x*b.x + a.y*b.y + a.z*b.z + a.w*b.w;
        }
        acc = warp_sum(acc);
        if (lane == 0) qs[i] = (acc + bq[h]) * QSCALE;
    }
    __syncthreads();
    float acc = 0.f;
#pragma unroll 8
    for (int i = 0; i < DH; i++)
        acc += qs[i] * Wk[(size_t)(i*NH + n)*MD + m];
    g_w8[m*NH + n] = acc;
}

// ---------------- k3: fused scores + online softmax + pooling (f32x2) ----------------
__global__ __launch_bounds__(TPB, 1) void k_main(const float* __restrict__ mem){
    extern __shared__ float sm[];
    float* rowbuf = sm;                          // 2*TR*MD floats
    u64*   part2  = (u64*)(sm + 2*TR*MD);        // TR*4*TPB u64 (== TR*NH*TPB floats)
    float* srow   = sm + 2*TR*MD + TR*NH*TPB;    // TR*NH
    float* esm    = srow + TR*NH;                // TR*NH
    float* scs    = esm + TR*NH;                 // NH
    int*   sflag  = (int*)(scs + NH);            // 1
    const int t = threadIdx.x, b = blockIdx.x;
    const int lane = t & 31, wid = t >> 5;

    const int baseCnt = NT / GB, rem = NT % GB;
    const int cnt   = baseCnt + (b < rem ? 1 : 0);
    const int start = b * baseCnt + (b < rem ? b : rem);

    // per-thread slice of w8 packed over head pairs: w2[k][j] = {w[k][2j], w[k][2j+1]}
    u64 w2[8][4];
#pragma unroll
    for (int k = 0; k < 8; k++){
        int c = (k < 4) ? (t*4 + k) : (1024 + t*4 + (k - 4));
        const float4* wp = (const float4*)(g_w8 + c*8);
        float4 a = wp[0], d4 = wp[1];
        w2[k][0] = pk(a.x, a.y);  w2[k][1] = pk(a.z, a.w);
        w2[k][2] = pk(d4.x, d4.y); w2[k][3] = pk(d4.z, d4.w);
    }
    // pooled accumulators packed over column pairs: p2[n][j] = {p[n][2j], p[n][2j+1]}
    u64 p2[8][4];
#pragma unroll
    for (int n = 0; n < 8; n++)
#pragma unroll
        for (int j = 0; j < 4; j++) p2[n][j] = 0ull;
    float mcur = -INFINITY, Zc = 0.f;   // live in warp0 lanes<8

    auto issue = [&](int tileIdx, int dbuf){
        const float* src = mem + (size_t)tileIdx * (TR*MD);
        float* dst = rowbuf + dbuf * (TR*MD);
#pragma unroll
        for (int j = 0; j < 16; j++){
            int idx = t + j*TPB;
            cp16(dst + idx*4, src + idx*4);
        }
    };
    if (cnt > 0) issue(start, 0);
    asm volatile("cp.async.commit_group;");
    if (cnt > 1) issue(start + 1, 1);
    asm volatile("cp.async.commit_group;");

    for (int it = 0; it < cnt; it++){
        asm volatile("cp.async.wait_group 1;");
        __syncthreads();
        const float* buf = rowbuf + (it & 1) * (TR*MD);

        // Phase A: packed partial scores (head pairs) for TR rows
#pragma unroll
        for (int r = 0; r < TR; r++){
            const float4* rp = (const float4*)(buf + r*MD + t*4);
            float4 r0 = rp[0], r1 = rp[256];
            u64 rvd[8] = {dup2(r0.x), dup2(r0.y), dup2(r0.z), dup2(r0.w),
                          dup2(r1.x), dup2(r1.y), dup2(r1.z), dup2(r1.w)};
            u64 acc2[4];
#pragma unroll
            for (int j = 0; j < 4; j++) acc2[j] = mul2(rvd[0], w2[0][j]);
#pragma unroll
            for (int k = 1; k < 8; k++)
#pragma unroll
                for (int j = 0; j < 4; j++) acc2[j] = fma2(rvd[k], w2[k][j], acc2[j]);
#pragma unroll
            for (int j = 0; j < 4; j++) part2[(r*4 + j)*TPB + t] = acc2[j];
        }
        __syncthreads();

        // Phase B: warp r reduces its row's 4 head-pairs over 256 threads
        {
            int r = wid;
#pragma unroll
            for (int j = 0; j < 4; j++){
                const u64* pp = part2 + (r*4 + j)*TPB;
                u64 v = pp[lane];
#pragma unroll
                for (int i = 1; i < 8; i++) v = add2(v, pp[lane + 32*i]);
                v = warp_sum2(v);
                if (lane == 0){
                    float lo, hi; upk(v, lo, hi);
                    srow[r*8 + 2*j]     = lo;
                    srow[r*8 + 2*j + 1] = hi;
                }
            }
        }
        __syncthreads();

        // Phase C: online-softmax bookkeeping (warp 0; lanes<8 do the work)
        if (wid == 0){
            float sc = 1.f;
            if (lane < 8){
                int n = lane;
                float tm = srow[n];
#pragma unroll
                for (int r = 1; r < TR; r++) tm = fmaxf(tm, srow[r*8 + n]);
                float mnew = fmaxf(mcur, tm);
                sc = __expf(mcur - mnew);   // 0 on first tile
                float zl = 0.f;
#pragma unroll
                for (int r = 0; r < TR; r++){
                    float e = __expf(srow[r*8 + n] - mnew);
                    esm[r*8 + n] = e;
                    zl += e;
                }
                Zc = Zc*sc + zl;
                mcur = mnew;
                scs[n] = sc;
            }
            unsigned bal = __ballot_sync(0xffffffffu, (lane < 8) ? (sc == 1.f) : true);
            if (lane == 0) *sflag = (bal == 0xffffffffu);
        }
        __syncthreads();

        // Phase D: (optional) rescale + packed weighted accumulation
        {
            if (!*sflag){
                const float4* sp = (const float4*)scs;
                float4 a = sp[0], d4 = sp[1];
                u64 s2[8] = {dup2(a.x), dup2(a.y), dup2(a.z), dup2(a.w),
                             dup2(d4.x), dup2(d4.y), dup2(d4.z), dup2(d4.w)};
#pragma unroll
                for (int n = 0; n < 8; n++)
#pragma unroll
                    for (int j = 0; j < 4; j++) p2[n][j] = mul2(s2[n], p2[n][j]);
            }
#pragma unroll
            for (int r = 0; r < TR; r++){
                const float4* rp = (const float4*)(buf + r*MD + t*4);
                float4 r0 = rp[0], r1 = rp[256];
                u64 rp2[4] = {pk(r0.x, r0.y), pk(r0.z, r0.w),
                              pk(r1.x, r1.y), pk(r1.z, r1.w)};
                const float4* ep = (const float4*)(esm + r*8);
                float4 e0 = ep[0], e1 = ep[1];
                u64 evd[8] = {dup2(e0.x), dup2(e0.y), dup2(e0.z), dup2(e0.w),
                              dup2(e1.x), dup2(e1.y), dup2(e1.z), dup2(e1.w)};
#pragma unroll
                for (int n = 0; n < 8; n++)
#pragma unroll
                    for (int j = 0; j < 4; j++) p2[n][j] = fma2(evd[n], rp2[j], p2[n][j]);
            }
        }
        __syncthreads();
        if (it + 2 < cnt) issue(start + it + 2, it & 1);
        asm volatile("cp.async.commit_group;");
    }

    // write per-block partial (m, Z, pooled)
    if (t < 8){ g_pm[b*8 + t] = mcur; g_pz[b*8 + t] = Zc; }
#pragma unroll
    for (int n = 0; n < 8; n++){
        float f0,f1,f2,f3,f4,f5,f6,f7;
        upk(p2[n][0], f0, f1); upk(p2[n][1], f2, f3);
        upk(p2[n][2], f4, f5); upk(p2[n][3], f6, f7);
        float* dst = g_pp + (size_t)(b*8 + n)*MD;
        ((float4*)dst)[t]          = make_float4(f0, f1, f2, f3);   // cols t*4..
        ((float4*)(dst + 1024))[t] = make_float4(f4, f5, f6, f7);   // cols 1024+t*4..
    }
}

// -------- k_comb (mz fused in): parallel weighted reduction of partials --------
#define CTPB 128
__global__ __launch_bounds__(CTPB) void k_comb(){
    int n   = blockIdx.x >> 4;                            // 8 heads
    int col = (blockIdx.x & 15) * CTPB + threadIdx.x;     // 16 col blocks
    int lane = threadIdx.x & 31, wid = threadIdx.x >> 5;
    __shared__ float S[GB];
    __shared__ float invZsh;
    if (wid == 0){
        float m = -INFINITY;
#pragma unroll
        for (int j = 0; j < 5; j++){
            int bb = lane + 32*j;
            if (bb < GB) m = fmaxf(m, g_pm[bb*8 + n]);
        }
        m = warp_max(m);
        float z = 0.f;
#pragma unroll
        for (int j = 0; j < 5; j++){
            int bb = lane + 32*j;
            if (bb < GB){
                float s = __expf(g_pm[bb*8 + n] - m);
                S[bb] = s;
                z += g_pz[bb*8 + n] * s;
            }
        }
        z = warp_sum(z);
        if (lane == 0) invZsh = 1.f / z;
    }
    __syncthreads();
    const float* base = g_pp + (size_t)n*MD + col;
    float acc = 0.f;
#pragma unroll 8
    for (int bb = 0; bb < GB; bb++)
        acc += S[bb] * base[(size_t)bb * (8*MD)];
    g_pooled[n*MD + col] = acc * invZsh;
}

// ---------- k5: feat[h] = pooled[h%8] . Wv[h,:] + bv[h] (warp/output) ----------
__global__ __launch_bounds__(TPB) void k_feat(const float* __restrict__ Wv,
                                              const float* __restrict__ bv){
    int lane = threadIdx.x & 31;
    int h = blockIdx.x * 8 + (threadIdx.x >> 5);
    int n = h & 7;
    const float4* wr = (const float4*)(Wv + (size_t)h*MD);
    const float4* pr = (const float4*)(g_pooled + n*MD);
    float acc = 0.f;
#pragma unroll
    for (int i = 0; i < 16; i++){
        float4 a = wr[lane + 32*i];
        float4 v = pr[lane + 32*i];
        acc += a.x*v.x + a.y*v.y + a.z*v.z + a.w*v.w;
    }
    acc = warp_sum(acc);
    if (lane == 0) g_feat[h] = acc + bv[h];
}

// ---------- k6: out = relu([x, feat] @ Wo^T + bo) (warp per output) ----------
__global__ __launch_bounds__(TPB) void k_out(const float* __restrict__ x,
                                             const float* __restrict__ Wo,
                                             const float* __restrict__ bo,
                                             float* __restrict__ out){
    int lane = threadIdx.x & 31;
    int o = blockIdx.x * 8 + (threadIdx.x >> 5);
    const float4* wr = (const float4*)(Wo + (size_t)o*(2*HDIM));
    const float4* xr = (const float4*)x;
    const float4* fr = (const float4*)g_feat;
    float acc = 0.f;
#pragma unroll
    for (int i = 0; i < 16; i++){
        int idx = lane + 32*i;
        float4 a = wr[idx];
        float4 v = (idx < 256) ? xr[idx] : fr[idx - 256];
        acc += a.x*v.x + a.y*v.y + a.z*v.z + a.w*v.w;
    }
    acc = warp_sum(acc);
    if (lane == 0) out[o] = fmaxf(acc + bo[o], 0.f);
}

extern "C" void kernel_launch(void* const* d_in, const int* in_sizes, int n_in,
                              void* d_out, int out_size){
    (void)in_sizes; (void)n_in; (void)out_size;
    const float* x   = (const float*)d_in[0];
    const float* mem = (const float*)d_in[1];
    const float* Wq  = (const float*)d_in[2];
    const float* bq  = (const float*)d_in[3];
    const float* Wk  = (const float*)d_in[4];
    // d_in[5] = bk: constant per head -> cancels in softmax, unused
    const float* Wv  = (const float*)d_in[6];
    const float* bv  = (const float*)d_in[7];
    const float* Wo  = (const float*)d_in[8];
    const float* bo  = (const float*)d_in[9];
    float* out = (float*)d_out;

    const size_t smem = (size_t)(2*TR*MD + TR*NH*TPB + 2*TR*NH + NH + 1) * sizeof(float);
    cudaFuncSetAttribute(k_main, cudaFuncAttributeMaxDynamicSharedMemorySize, (int)smem);

    k_w8  <<<(MD/TPB)*NH,   TPB>>>(x, Wq, bq, Wk);
    k_main<<<GB,            TPB, smem>>>(mem);
    k_comb<<<NH*(MD/CTPB),  CTPB>>>();
    k_feat<<<HDIM/8,        TPB>>>(Wv, bv);
    k_out <<<HDIM/8,        TPB>>>(x, Wo, bo, out);
}

// round 8
// speedup vs baseline: 1.1657x; 1.1657x over previous
#include <cuda_runtime.h>
#include <math.h>
#include <stdint.h>

#define HDIM 1024
#define MD   2048
#define LMEM 16384
#define NH   8
#define DH   128
#define TPB  256
#define TR   8
#define NT   (LMEM/TR)     // 2048 tiles
#define GB   152           // GB300 has 152 SMs
#define QSCALE 0.08838834764831845f   // 1/sqrt(128)

// __device__ scratch (no allocations allowed)
__device__ float g_q[HDIM];
__device__ float g_w8[MD*NH];
__device__ float g_pm[GB*NH];
__device__ float g_pz[GB*NH];
__device__ float g_pp[GB*NH*MD];
__device__ float g_pooled[NH*MD];
__device__ float g_feat[HDIM];

__device__ __forceinline__ float warp_sum(float v){
#pragma unroll
    for (int o = 16; o; o >>= 1) v += __shfl_xor_sync(0xffffffffu, v, o);
    return v;
}
__device__ __forceinline__ float warp_max(float v){
#pragma unroll
    for (int o = 16; o; o >>= 1) v = fmaxf(v, __shfl_xor_sync(0xffffffffu, v, o));
    return v;
}

__device__ __forceinline__ void cp16(float* dst, const float* src){
    uint32_t s = (uint32_t)__cvta_generic_to_shared(dst);
    asm volatile("cp.async.cg.shared.global [%0], [%1], 16;" :: "r"(s), "l"(src));
}

// ---------------- k1: q = x @ Wq^T + bq  (warp per output) ----------------
__global__ __launch_bounds__(TPB) void k_q(const float* __restrict__ x,
                                           const float* __restrict__ Wq,
                                           const float* __restrict__ bq){
    int lane = threadIdx.x & 31;
    int h = blockIdx.x * 8 + (threadIdx.x >> 5);
    const float4* xr = (const float4*)x;
    const float4* wr = (const float4*)(Wq + (size_t)h * HDIM);
    float acc = 0.f;
#pragma unroll
    for (int i = 0; i < 8; i++){
        float4 a = wr[lane + 32*i];
        float4 b = xr[lane + 32*i];
        acc += a.x*b.x + a.y*b.y + a.z*b.z + a.w*b.w;
    }
    acc = warp_sum(acc);
    if (lane == 0) g_q[h] = acc + bq[h];
}

// ---------- k2: w8[m][n] = QSCALE * sum_i q[i*8+n] * Wk[i*8+n][m] ----------
// 128 blocks x 128 threads: full-chip coverage, 64KB DRAM per block.
#define WTPB 128
__global__ __launch_bounds__(WTPB) void k_w8(const float* __restrict__ Wk){
    int n = blockIdx.x & 7;
    int m = (blockIdx.x >> 3) * WTPB + threadIdx.x;
    __shared__ float qs[DH];
    qs[threadIdx.x] = g_q[threadIdx.x * NH + n] * QSCALE;   // 128 threads == DH
    __syncthreads();
    float acc = 0.f;
#pragma unroll 8
    for (int i = 0; i < DH; i++)
        acc += qs[i] * Wk[(size_t)(i*NH + n)*MD + m];
    g_w8[m*NH + n] = acc;
}

// ---------------- k3: fused scores + online softmax + pooling ----------------
__global__ __launch_bounds__(TPB, 1) void k_main(const float* __restrict__ mem){
    extern __shared__ float sm[];
    float* rowbuf = sm;                       // 2*TR*MD
    float* part   = sm + 2*TR*MD;             // TR*NH*TPB
    float* srow   = part + TR*NH*TPB;         // TR*NH
    float* esm    = srow + TR*NH;             // TR*NH
    float* scs    = esm + TR*NH;              // NH
    int*   sflag  = (int*)(scs + NH);         // 1
    const int t = threadIdx.x, b = blockIdx.x;
    const int lane = t & 31, wid = t >> 5;

    const int baseCnt = NT / GB, rem = NT % GB;
    const int cnt   = baseCnt + (b < rem ? 1 : 0);
    const int start = b * baseCnt + (b < rem ? b : rem);

    // per-thread slice of w8: [k][n]
    float w[8][8];
#pragma unroll
    for (int k = 0; k < 8; k++){
        int c = (k < 4) ? (t*4 + k) : (1024 + t*4 + (k - 4));
        const float4* wp = (const float4*)(g_w8 + c*8);
        float4 a = wp[0], d4 = wp[1];
        w[k][0]=a.x;  w[k][1]=a.y;  w[k][2]=a.z;  w[k][3]=a.w;
        w[k][4]=d4.x; w[k][5]=d4.y; w[k][6]=d4.z; w[k][7]=d4.w;
    }
    float p[8][8];   // [n][k] pooled accumulators
#pragma unroll
    for (int n = 0; n < 8; n++)
#pragma unroll
        for (int k = 0; k < 8; k++) p[n][k] = 0.f;
    float mcur = -INFINITY, Zc = 0.f;   // live in warp0 lanes<8

    auto issue = [&](int tileIdx, int dbuf){
        const float* src = mem + (size_t)tileIdx * (TR*MD);
        float* dst = rowbuf + dbuf * (TR*MD);
#pragma unroll
        for (int j = 0; j < 16; j++){
            int idx = t + j*TPB;
            cp16(dst + idx*4, src + idx*4);
        }
    };
    if (cnt > 0) issue(start, 0);
    asm volatile("cp.async.commit_group;");
    if (cnt > 1) issue(start + 1, 1);
    asm volatile("cp.async.commit_group;");

    for (int it = 0; it < cnt; it++){
        asm volatile("cp.async.wait_group 1;");
        __syncthreads();
        const float* buf = rowbuf + (it & 1) * (TR*MD);

        // Phase A: per-thread partial scores for all TR rows x 8 heads
#pragma unroll
        for (int r = 0; r < TR; r++){
            const float4* rp = (const float4*)(buf + r*MD + t*4);
            float4 r0 = rp[0], r1 = rp[256];
            float rv[8] = {r0.x,r0.y,r0.z,r0.w, r1.x,r1.y,r1.z,r1.w};
            float acc[8];
#pragma unroll
            for (int n = 0; n < 8; n++) acc[n] = rv[0]*w[0][n];
#pragma unroll
            for (int k = 1; k < 8; k++)
#pragma unroll
                for (int n = 0; n < 8; n++) acc[n] += rv[k]*w[k][n];
#pragma unroll
            for (int n = 0; n < 8; n++) part[(r*8 + n)*TPB + t] = acc[n];
        }
        __syncthreads();

        // Phase B: warp r reduces its row's 8 head-partials over 256 threads
        {
            int r = wid;
#pragma unroll
            for (int n = 0; n < 8; n++){
                const float4* pp = (const float4*)(part + (r*8 + n)*TPB);
                float4 a = pp[lane*2], c4 = pp[lane*2 + 1];
                float v = (a.x + a.y) + (a.z + a.w) + (c4.x + c4.y) + (c4.z + c4.w);
                v = warp_sum(v);
                if (lane == 0) srow[r*8 + n] = v;
            }
        }
        __syncthreads();

        // Phase C: online-softmax bookkeeping (warp 0; lanes<8 do the work)
        if (wid == 0){
            float sc = 1.f;
            if (lane < 8){
                int n = lane;
                float tm = srow[n];
#pragma unroll
                for (int r = 1; r < TR; r++) tm = fmaxf(tm, srow[r*8 + n]);
                float mnew = fmaxf(mcur, tm);
                sc = __expf(mcur - mnew);   // 0 on first tile
                float zl = 0.f;
#pragma unroll
                for (int r = 0; r < TR; r++){
                    float e = __expf(srow[r*8 + n] - mnew);
                    esm[r*8 + n] = e;
                    zl += e;
                }
                Zc = Zc*sc + zl;
                mcur = mnew;
                scs[n] = sc;
            }
            unsigned bal = __ballot_sync(0xffffffffu, (lane < 8) ? (sc == 1.f) : true);
            if (lane == 0) *sflag = (bal == 0xffffffffu);
        }
        __syncthreads();

        // Phase D: (conditional) rescale + weighted accumulation of rows
        {
            if (!*sflag){
                float s8[8];
                const float4* sp = (const float4*)scs;
                float4 a = sp[0], d4 = sp[1];
                s8[0]=a.x; s8[1]=a.y; s8[2]=a.z; s8[3]=a.w;
                s8[4]=d4.x; s8[5]=d4.y; s8[6]=d4.z; s8[7]=d4.w;
#pragma unroll
                for (int n = 0; n < 8; n++)
#pragma unroll
                    for (int k = 0; k < 8; k++) p[n][k] *= s8[n];
            }
#pragma unroll
            for (int r = 0; r < TR; r++){
                const float4* rp = (const float4*)(buf + r*MD + t*4);
                float4 r0 = rp[0], r1 = rp[256];
                float rv[8] = {r0.x,r0.y,r0.z,r0.w, r1.x,r1.y,r1.z,r1.w};
                const float4* ep = (const float4*)(esm + r*8);
                float4 e0 = ep[0], e1 = ep[1];
                float ev[8] = {e0.x,e0.y,e0.z,e0.w, e1.x,e1.y,e1.z,e1.w};
#pragma unroll
                for (int n = 0; n < 8; n++)
#pragma unroll
                    for (int k = 0; k < 8; k++) p[n][k] += ev[n]*rv[k];
            }
        }
        __syncthreads();
        if (it + 2 < cnt) issue(start + it + 2, it & 1);
        asm volatile("cp.async.commit_group;");
    }

    // write per-block partial (m, Z, pooled)
    if (t < 8){ g_pm[b*8 + t] = mcur; g_pz[b*8 + t] = Zc; }
#pragma unroll
    for (int n = 0; n < 8; n++){
        float4 s0 = make_float4(p[n][0], p[n][1], p[n][2], p[n][3]);
        float4 s1 = make_float4(p[n][4], p[n][5], p[n][6], p[n][7]);
        float* dst = g_pp + (size_t)(b*8 + n)*MD;
        ((float4*)dst)[t]          = s0;        // cols t*4 ..
        ((float4*)(dst + 1024))[t] = s1;        // cols 1024+t*4 ..
    }
}

// -------- k_comb (mz fused in): parallel weighted reduction of partials --------
#define CTPB 128
__global__ __launch_bounds__(CTPB) void k_comb(){
    int n   = blockIdx.x >> 4;                            // 8 heads
    int col = (blockIdx.x & 15) * CTPB + threadIdx.x;     // 16 col blocks
    int lane = threadIdx.x & 31, wid = threadIdx.x >> 5;
    __shared__ float S[GB];
    __shared__ float invZsh;
    if (wid == 0){
        float m = -INFINITY;
#pragma unroll
        for (int j = 0; j < 5; j++){
            int bb = lane + 32*j;
            if (bb < GB) m = fmaxf(m, g_pm[bb*8 + n]);
        }
        m = warp_max(m);
        float z = 0.f;
#pragma unroll
        for (int j = 0; j < 5; j++){
            int bb = lane + 32*j;
            if (bb < GB){
                float s = __expf(g_pm[bb*8 + n] - m);
                S[bb] = s;
                z += g_pz[bb*8 + n] * s;
            }
        }
        z = warp_sum(z);
        if (lane == 0) invZsh = 1.f / z;
    }
    __syncthreads();
    const float* base = g_pp + (size_t)n*MD + col;
    float acc = 0.f;
#pragma unroll 8
    for (int bb = 0; bb < GB; bb++)
        acc += S[bb] * base[(size_t)bb * (8*MD)];
    g_pooled[n*MD + col] = acc * invZsh;
}

// ---- k5: feat[h] = pooled[h%8].Wv[h,:] + bv[h]  (2 warps per output) ----
__global__ __launch_bounds__(TPB) void k_feat(const float* __restrict__ Wv,
                                              const float* __restrict__ bv){
    __shared__ float sh[4][2];
    int lane = threadIdx.x & 31, wid = threadIdx.x >> 5;
    int local = wid >> 1, half = wid & 1;
    int h = blockIdx.x * 4 + local;
    int n = h & 7;
    const float4* wr = (const float4*)(Wv + (size_t)h*MD) + half*256;
    const float4* pr = (const float4*)(g_pooled + (size_t)n*MD) + half*256;
    float acc = 0.f;
#pragma unroll
    for (int i = 0; i < 8; i++){
        float4 a = wr[lane + 32*i];
        float4 v = pr[lane + 32*i];
        acc += a.x*v.x + a.y*v.y + a.z*v.z + a.w*v.w;
    }
    acc = warp_sum(acc);
    if (lane == 0) sh[local][half] = acc;
    __syncthreads();
    if (threadIdx.x < 4){
        int hh = blockIdx.x * 4 + threadIdx.x;
        g_feat[hh] = sh[threadIdx.x][0] + sh[threadIdx.x][1] + bv[hh];
    }
}

// ---- k6: out = relu([x,feat] @ Wo^T + bo)  (2 warps per output) ----
__global__ __launch_bounds__(TPB) void k_out(const float* __restrict__ x,
                                             const float* __restrict__ Wo,
                                             const float* __restrict__ bo,
                                             float* __restrict__ out){
    __shared__ float sh[4][2];
    int lane = threadIdx.x & 31, wid = threadIdx.x >> 5;
    int local = wid >> 1, half = wid & 1;
    int o = blockIdx.x * 4 + local;
    const float4* wr = (const float4*)(Wo + (size_t)o*(2*HDIM)) + half*256;
    const float4* vr = half ? (const float4*)g_feat : (const float4*)x;
    float acc = 0.f;
#pragma unroll
    for (int i = 0; i < 8; i++){
        int idx = lane + 32*i;
        float4 a = wr[idx];
        float4 v = vr[idx];
        acc += a.x*v.x + a.y*v.y + a.z*v.z + a.w*v.w;
    }
    acc = warp_sum(acc);
    if (lane == 0) sh[local][half] = acc;
    __syncthreads();
    if (threadIdx.x < 4){
        int oo = blockIdx.x * 4 + threadIdx.x;
        out[oo] = fmaxf(sh[threadIdx.x][0] + sh[threadIdx.x][1] + bo[oo], 0.f);
    }
}

extern "C" void kernel_launch(void* const* d_in, const int* in_sizes, int n_in,
                              void* d_out, int out_size){
    (void)in_sizes; (void)n_in; (void)out_size;
    const float* x   = (const float*)d_in[0];
    const float* mem = (const float*)d_in[1];
    const float* Wq  = (const float*)d_in[2];
    const float* bq  = (const float*)d_in[3];
    const float* Wk  = (const float*)d_in[4];
    // d_in[5] = bk: constant per head -> cancels in softmax, unused
    const float* Wv  = (const float*)d_in[6];
    const float* bv  = (const float*)d_in[7];
    const float* Wo  = (const float*)d_in[8];
    const float* bo  = (const float*)d_in[9];
    float* out = (float*)d_out;

    const size_t smem = (size_t)(2*TR*MD + TR*NH*TPB + 2*TR*NH + NH + 1) * sizeof(float);
    cudaFuncSetAttribute(k_main, cudaFuncAttributeMaxDynamicSharedMemorySize, (int)smem);

    k_q   <<<HDIM/8,        TPB>>>(x, Wq, bq);
    k_w8  <<<(MD/WTPB)*NH,  WTPB>>>(Wk);
    k_main<<<GB,            TPB, smem>>>(mem);
    k_comb<<<NH*(MD/CTPB),  CTPB>>>();
    k_feat<<<HDIM/4,        TPB>>>(Wv, bv);
    k_out <<<(2*HDIM)/8,    TPB>>>(x, Wo, bo, out);
}